// round 7
// baseline (speedup 1.0000x reference)
#include <cuda_runtime.h>
#include <cuda_bf16.h>
#include <cstdint>
#include <cstddef>

// Problem constants
#define BB   64
#define TT   2048
#define DD   256
#define HH   256
#define OO   256
#define FH   1024   // 4*H

// Phase-2 partitioning: 16 clusters x 8 CTAs = 128 CTAs.
// Cluster owns 4 batches, split into set A = {0,1} and set B = {2,3}.
// CTA rank r owns hidden units [r*32, r*32+32) -> 128 gate columns.
#define CL   8      // CTAs per cluster
#define GB   4      // batches per cluster
#define SB   2      // batches per set
#define HU   32     // hidden units per CTA
#define NC   128    // gate columns per CTA (4*HU)

// Device-global scratch (allocation-free per harness rules)
__device__ float g_G[(size_t)BB * TT * FH];    // 536 MB: x@Wih + bh
__device__ float g_Hall[(size_t)BB * TT * HH]; // 134 MB: every h_t

// ---------------------------------------------------------------------------
// fp32 GEMM: C[M,N] = A[M,K] @ B[K,N] + bias[N]
// 128x128 tile, 256 threads, 8x8 micro-tile, K-chunks of 16.
// ---------------------------------------------------------------------------
__global__ __launch_bounds__(256, 2) void gemm_kernel(
    const float* __restrict__ A, const float* __restrict__ B,
    const float* __restrict__ bias, float* __restrict__ C,
    int M, int N, int K)
{
    __shared__ float As[16][132];
    __shared__ float Bs[16][132];

    const int tid  = threadIdx.x;
    const int m0   = blockIdx.y * 128;
    const int n0   = blockIdx.x * 128;
    const int ty   = tid >> 4, tx = tid & 15;
    const int arow = tid >> 1, aseg = (tid & 1) * 8;
    const int brow = tid >> 4, bcol = (tid & 15) * 4;

    float acc[8][8];
#pragma unroll
    for (int i = 0; i < 8; i++)
#pragma unroll
        for (int j = 0; j < 8; j++) acc[i][j] = 0.f;

    for (int k0 = 0; k0 < K; k0 += 16) {
        float4 av0 = *(const float4*)&A[(size_t)(m0 + arow) * K + k0 + aseg];
        float4 av1 = *(const float4*)&A[(size_t)(m0 + arow) * K + k0 + aseg + 4];
        float4 bv0 = *(const float4*)&B[(size_t)(k0 + brow) * N + n0 + bcol];
        float4 bv1 = *(const float4*)&B[(size_t)(k0 + brow) * N + n0 + bcol + 64];

        As[aseg + 0][arow] = av0.x; As[aseg + 1][arow] = av0.y;
        As[aseg + 2][arow] = av0.z; As[aseg + 3][arow] = av0.w;
        As[aseg + 4][arow] = av1.x; As[aseg + 5][arow] = av1.y;
        As[aseg + 6][arow] = av1.z; As[aseg + 7][arow] = av1.w;
        *(float4*)&Bs[brow][bcol]      = bv0;
        *(float4*)&Bs[brow][bcol + 64] = bv1;
        __syncthreads();

#pragma unroll
        for (int k = 0; k < 16; k++) {
            float a[8], b[8];
            *(float4*)&a[0] = *(const float4*)&As[k][ty * 8];
            *(float4*)&a[4] = *(const float4*)&As[k][ty * 8 + 4];
            *(float4*)&b[0] = *(const float4*)&Bs[k][tx * 8];
            *(float4*)&b[4] = *(const float4*)&Bs[k][tx * 8 + 4];
#pragma unroll
            for (int i = 0; i < 8; i++)
#pragma unroll
                for (int j = 0; j < 8; j++)
                    acc[i][j] = fmaf(a[i], b[j], acc[i][j]);
        }
        __syncthreads();
    }

#pragma unroll
    for (int i = 0; i < 8; i++) {
        size_t row = (size_t)(m0 + ty * 8 + i);
#pragma unroll
        for (int j = 0; j < 8; j += 4) {
            int col = n0 + tx * 8 + j;
            float4 v;
            v.x = acc[i][j + 0] + bias[col + 0];
            v.y = acc[i][j + 1] + bias[col + 1];
            v.z = acc[i][j + 2] + bias[col + 2];
            v.w = acc[i][j + 3] + bias[col + 3];
            *(float4*)&C[row * N + col] = v;
        }
    }
}

// ---------------------------------------------------------------------------
// PTX helpers
// ---------------------------------------------------------------------------
__device__ __forceinline__ uint32_t smem_u32(const void* p) {
    uint32_t a;
    asm("{ .reg .u64 t; cvta.to.shared.u64 t, %1; cvt.u32.u64 %0, t; }"
        : "=r"(a) : "l"(p));
    return a;
}

__device__ __forceinline__ void mbar_init(uint32_t addr, uint32_t count) {
    asm volatile("mbarrier.init.shared.b64 [%0], %1;" :: "r"(addr), "r"(count) : "memory");
}

// Release-arrive (cluster scope) on the mbarrier at the same SMEM offset in
// CTA `rank` of this cluster.
__device__ __forceinline__ void mbar_arrive_cluster(uint32_t local_addr, uint32_t rank) {
    asm volatile(
        "{\n\t"
        ".reg .b32 ra;\n\t"
        "mapa.shared::cluster.u32 ra, %0, %1;\n\t"
        "mbarrier.arrive.release.cluster.shared::cluster.b64 _, [ra];\n\t"
        "}"
        :: "r"(local_addr), "r"(rank) : "memory");
}

// Acquire-wait (cluster scope) on local mbarrier, phase parity `par`.
__device__ __forceinline__ void mbar_wait_cluster(uint32_t addr, uint32_t par) {
    asm volatile(
        "{\n\t"
        ".reg .pred P;\n\t"
        "WL_%=:\n\t"
        "mbarrier.try_wait.parity.acquire.cluster.shared::cta.b64 P, [%0], %1, 0x989680;\n\t"
        "@P bra.uni WD_%=;\n\t"
        "bra.uni WL_%=;\n\t"
        "WD_%=:\n\t"
        "}"
        :: "r"(addr), "r"(par) : "memory");
}

// Vector DSMEM store: 16 bytes to CTA `rank` of this cluster.
__device__ __forceinline__ void st_cluster_v4(uint32_t local_addr, uint32_t rank, float4 v) {
    asm volatile(
        "{\n\t"
        ".reg .b32 ra;\n\t"
        "mapa.shared::cluster.u32 ra, %0, %1;\n\t"
        "st.shared::cluster.v4.f32 [ra], {%2, %3, %4, %5};\n\t"
        "}"
        :: "r"(local_addr), "r"(rank), "f"(v.x), "f"(v.y), "f"(v.z), "f"(v.w)
        : "memory");
}

__device__ __forceinline__ float sigm(float x) {
    return __fdividef(1.f, 1.f + __expf(-x));
}
__device__ __forceinline__ float tanhe(float x) {
    // tanh(x) = 1 - 2/(e^{2x}+1); saturates correctly at +-inf.
    return 1.f - __fdividef(2.f, __expf(2.f * x) + 1.f);
}

// ---------------------------------------------------------------------------
// Phase 2: persistent LSTM recurrence, pipelined two-set cluster version.
// grid = 128 CTAs as 16 clusters of 8. Cluster cid owns batches
// [cid*4, cid*4+4): set A = first 2, set B = last 2. Rank r owns hidden
// units [r*32, r*32+32).
// Per iteration t: (wait A exch t-1) -> GEMV_A -> pointwise A -> stage ->
// v4 DSMEM scatter to all 8 CTAs -> arrive A; then the same for B. Each
// set's exchange latency (scatter flight + arrival skew + barrier) hides
// under the OTHER set's ~1300-cycle half-step.
// ---------------------------------------------------------------------------
__global__ __launch_bounds__(256, 1) __cluster_dims__(CL, 1, 1)
void lstm_kernel(const float* __restrict__ c0, const float* __restrict__ h0,
                 const float* __restrict__ Whh)
{
    const int cid  = blockIdx.x / CL;
    uint32_t rr;
    asm("mov.u32 %0, %%cluster_ctarank;" : "=r"(rr));
    const int r    = (int)rr;
    const int tid  = threadIdx.x;
    const int half = tid >> 7;          // k-half: [half*128, half*128+128)
    const int c    = tid & 127;         // gate col within CTA
    const int gate = c >> 5, u = c & 31;
    const int gcol = gate * 256 + r * HU + u;

    __shared__ float hA[2][SB][HH];     // 4 KB double-buffered h, set A
    __shared__ float hB[2][SB][HH];     // 4 KB, set B
    __shared__ float red[2][SB][NC];    // 2 KB k-half partials (reused A/B)
    __shared__ float stage[SB * HU];    // 256 B scatter staging (reused A/B)
    __shared__ alignas(8) unsigned long long mbarA_s, mbarB_s;

    const uint32_t mbarA = smem_u32(&mbarA_s);
    const uint32_t mbarB = smem_u32(&mbarB_s);

    // One-time: Whh column slice into registers
    float w[128];
#pragma unroll
    for (int i = 0; i < 128; i++)
        w[i] = Whh[(size_t)(half * 128 + i) * FH + gcol];

    // h0 into buffer 0 of both sets
    for (int idx = tid; idx < SB * HH; idx += 256) {
        int b = idx >> 8, k = idx & 255;
        hA[0][b][k] = h0[(size_t)(cid * GB + b) * HH + k];
        hB[0][b][k] = h0[(size_t)(cid * GB + SB + b) * HH + k];
    }

    // Pointwise-thread state (tid < 64): pb = batch-in-set, pu = unit
    float cA = 0.f, cB = 0.f;
    int pb = 0, pu = 0;
    size_t gbA = 0, gbB = 0, haA = 0, haB = 0;
    if (tid < 64) {
        pb = tid >> 5; pu = tid & 31;
        const int bA = cid * GB + pb, bO = cid * GB + SB + pb;
        cA = c0[(size_t)bA * HH + r * HU + pu];
        cB = c0[(size_t)bO * HH + r * HU + pu];
        gbA = (size_t)bA * TT * FH + r * HU + pu;
        gbB = (size_t)bO * TT * FH + r * HU + pu;
        haA = (size_t)bA * TT * HH + r * HU + pu;
        haB = (size_t)bO * TT * HH + r * HU + pu;
    }

    if (tid == 0) { mbar_init(mbarA, CL); mbar_init(mbarB, CL); }
    __syncthreads();
    // All cluster CTAs' mbarriers live before any remote arrive.
    asm volatile("barrier.cluster.arrive.aligned;" ::: "memory");
    asm volatile("barrier.cluster.wait.aligned;" ::: "memory");

    for (int t = 0; t < TT; t++) {
        const int cur = t & 1, nxt = cur ^ 1;

        // Prefetch both sets' x@Wih+bh contributions (DRAM, consumed later)
        float pAi = 0.f, pAf = 0.f, pAg = 0.f, pAo = 0.f;
        float pBi = 0.f, pBf = 0.f, pBg = 0.f, pBo = 0.f;
        if (tid < 64) {
            const float* ga = &g_G[gbA + (size_t)t * FH];
            const float* gb = &g_G[gbB + (size_t)t * FH];
            pAi = ga[0]; pAf = ga[256]; pAg = ga[512]; pAo = ga[768];
            pBi = gb[0]; pBf = gb[256]; pBg = gb[512]; pBo = gb[768];
        }

        // ================= SET A half-step =================
        if (t > 0) mbar_wait_cluster(mbarA, (uint32_t)((t - 1) & 1));

        {   // GEMV over my k-half, 2 batches (broadcast LDS, 4 acc chains)
            const float4* h0p = (const float4*)&hA[cur][0][half * 128];
            const float4* h1p = (const float4*)&hA[cur][1][half * 128];
            float s00 = 0.f, s01 = 0.f, s10 = 0.f, s11 = 0.f;
#pragma unroll
            for (int i = 0; i < 32; i += 2) {
                float4 v0 = h0p[i],     v1 = h1p[i];
                float4 u0 = h0p[i + 1], u1 = h1p[i + 1];
                s00 = fmaf(v0.x, w[4*i+0], s00); s00 = fmaf(v0.y, w[4*i+1], s00);
                s00 = fmaf(v0.z, w[4*i+2], s00); s00 = fmaf(v0.w, w[4*i+3], s00);
                s10 = fmaf(v1.x, w[4*i+0], s10); s10 = fmaf(v1.y, w[4*i+1], s10);
                s10 = fmaf(v1.z, w[4*i+2], s10); s10 = fmaf(v1.w, w[4*i+3], s10);
                s01 = fmaf(u0.x, w[4*i+4], s01); s01 = fmaf(u0.y, w[4*i+5], s01);
                s01 = fmaf(u0.z, w[4*i+6], s01); s01 = fmaf(u0.w, w[4*i+7], s01);
                s11 = fmaf(u1.x, w[4*i+4], s11); s11 = fmaf(u1.y, w[4*i+5], s11);
                s11 = fmaf(u1.z, w[4*i+6], s11); s11 = fmaf(u1.w, w[4*i+7], s11);
            }
            red[half][0][c] = s00 + s01;
            red[half][1][c] = s10 + s11;
        }
        __syncthreads();

        if (tid < 64) {
            float vi = pAi + red[0][pb][pu]      + red[1][pb][pu];
            float vf = pAf + red[0][pb][32 + pu] + red[1][pb][32 + pu];
            float vg = pAg + red[0][pb][64 + pu] + red[1][pb][64 + pu];
            float vo = pAo + red[0][pb][96 + pu] + red[1][pb][96 + pu];
            cA = sigm(vf) * cA + sigm(vi) * tanhe(vg);
            float hh = sigm(vo) * tanhe(cA);
            g_Hall[haA + (size_t)t * HH] = hh;
            stage[pb * HU + pu] = hh;
        }
        __syncthreads();

        if (tid < 128) {   // v4 DSMEM scatter: 8 ranks x 16B x (2 batches)
            int rank = tid >> 4, j = tid & 15;
            int sb = j >> 3, qo = (j & 7) * 4;
            float4 sv = *(const float4*)&stage[sb * HU + qo];
            uint32_t la = smem_u32(&hA[nxt][sb][r * HU + qo]);
            st_cluster_v4(la, (uint32_t)rank, sv);
        }
        __syncthreads();
        if (tid < CL) mbar_arrive_cluster(mbarA, (uint32_t)tid);

        // ================= SET B half-step =================
        if (t > 0) mbar_wait_cluster(mbarB, (uint32_t)((t - 1) & 1));

        {
            const float4* h0p = (const float4*)&hB[cur][0][half * 128];
            const float4* h1p = (const float4*)&hB[cur][1][half * 128];
            float s00 = 0.f, s01 = 0.f, s10 = 0.f, s11 = 0.f;
#pragma unroll
            for (int i = 0; i < 32; i += 2) {
                float4 v0 = h0p[i],     v1 = h1p[i];
                float4 u0 = h0p[i + 1], u1 = h1p[i + 1];
                s00 = fmaf(v0.x, w[4*i+0], s00); s00 = fmaf(v0.y, w[4*i+1], s00);
                s00 = fmaf(v0.z, w[4*i+2], s00); s00 = fmaf(v0.w, w[4*i+3], s00);
                s10 = fmaf(v1.x, w[4*i+0], s10); s10 = fmaf(v1.y, w[4*i+1], s10);
                s10 = fmaf(v1.z, w[4*i+2], s10); s10 = fmaf(v1.w, w[4*i+3], s10);
                s01 = fmaf(u0.x, w[4*i+4], s01); s01 = fmaf(u0.y, w[4*i+5], s01);
                s01 = fmaf(u0.z, w[4*i+6], s01); s01 = fmaf(u0.w, w[4*i+7], s01);
                s11 = fmaf(u1.x, w[4*i+4], s11); s11 = fmaf(u1.y, w[4*i+5], s11);
                s11 = fmaf(u1.z, w[4*i+6], s11); s11 = fmaf(u1.w, w[4*i+7], s11);
            }
            red[half][0][c] = s00 + s01;
            red[half][1][c] = s10 + s11;
        }
        __syncthreads();

        if (tid < 64) {
            float vi = pBi + red[0][pb][pu]      + red[1][pb][pu];
            float vf = pBf + red[0][pb][32 + pu] + red[1][pb][32 + pu];
            float vg = pBg + red[0][pb][64 + pu] + red[1][pb][64 + pu];
            float vo = pBo + red[0][pb][96 + pu] + red[1][pb][96 + pu];
            cB = sigm(vf) * cB + sigm(vi) * tanhe(vg);
            float hh = sigm(vo) * tanhe(cB);
            g_Hall[haB + (size_t)t * HH] = hh;
            stage[pb * HU + pu] = hh;
        }
        __syncthreads();

        if (tid < 128) {
            int rank = tid >> 4, j = tid & 15;
            int sb = j >> 3, qo = (j & 7) * 4;
            float4 sv = *(const float4*)&stage[sb * HU + qo];
            uint32_t la = smem_u32(&hB[nxt][sb][r * HU + qo]);
            st_cluster_v4(la, (uint32_t)rank, sv);
        }
        __syncthreads();
        if (tid < CL) mbar_arrive_cluster(mbarB, (uint32_t)tid);
    }

    // No CTA may exit while peers' scatters targeting it are in flight.
    asm volatile("barrier.cluster.arrive.aligned;" ::: "memory");
    asm volatile("barrier.cluster.wait.aligned;" ::: "memory");
}

// ---------------------------------------------------------------------------
// Launch: G = x@Wih + bh -> LSTM recurrence -> Y = Hall@Wout + bout
// Inputs (metadata order): x, c0, h0, Wih, Whh, bh, Wout, bout
// ---------------------------------------------------------------------------
extern "C" void kernel_launch(void* const* d_in, const int* in_sizes, int n_in,
                              void* d_out, int out_size)
{
    const float* x    = (const float*)d_in[0];
    const float* c0   = (const float*)d_in[1];
    const float* h0   = (const float*)d_in[2];
    const float* Wih  = (const float*)d_in[3];
    const float* Whh  = (const float*)d_in[4];
    const float* bh   = (const float*)d_in[5];
    const float* Wout = (const float*)d_in[6];
    const float* bout = (const float*)d_in[7];
    float* Y = (float*)d_out;

    float* Gp = nullptr;
    float* Hp = nullptr;
    cudaGetSymbolAddress((void**)&Gp, g_G);
    cudaGetSymbolAddress((void**)&Hp, g_Hall);

    // Phase 1: G[B*T, 4H] = x[B*T, D] @ Wih[D, 4H] + bh
    {
        dim3 grid(FH / 128, (BB * TT) / 128);
        gemm_kernel<<<grid, 256>>>(x, Wih, bh, Gp, BB * TT, FH, DD);
    }

    // Phase 2: sequential LSTM over T steps (16 clusters x 8 CTAs)
    lstm_kernel<<<(BB / GB) * CL, 256>>>(c0, h0, Whh);

    // Phase 3: Y[B*T, O] = Hall[B*T, H] @ Wout[H, O] + bout
    {
        dim3 grid(OO / 128, (BB * TT) / 128);
        gemm_kernel<<<grid, 256>>>(Hp, Wout, bout, Y, BB * TT, OO, HH);
    }
}

// round 8
// speedup vs baseline: 1.3923x; 1.3923x over previous
#include <cuda_runtime.h>
#include <cuda_bf16.h>
#include <cstdint>
#include <cstddef>

// Problem constants
#define BB   64
#define TT   2048
#define DD   256
#define HH   256
#define OO   256
#define FH   1024   // 4*H

// Phase-2 partitioning: 8 batch groups x 16 CTAs = 128 CTAs, 512 threads.
// Group g owns batches [g*8, g*8+8) as 4 batch-PAIRS (f32x2 lanes).
// CTA r owns hidden units [r*16, r*16+16) -> 64 gate columns.
#define NGRP 8      // batch groups
#define GBP  4      // batch pairs per group (8 batches)
#define RC   16     // CTAs per group
#define HU   16     // hidden units per CTA
#define NCC  64     // gate columns per CTA
#define NTH  512    // threads per phase-2 CTA
#define KQ   8      // k-slices (each 32 wide)

// Device-global scratch (allocation-free per harness rules)
__device__ float    g_G[(size_t)BB * TT * FH];     // 536 MB: x@Wih + bh
__device__ float    g_Hall[(size_t)BB * TT * HH];  // 134 MB: every h_t (phase 3)
__device__ float    g_Hx[2][NGRP][GBP][2 * HH];    // 128 KB L2-resident exchange ring
__device__ unsigned g_ctr[NGRP];

// ---------------------------------------------------------------------------
__global__ void init_kernel() {
    if (threadIdx.x < NGRP) g_ctr[threadIdx.x] = 0u;
}

// ---------------------------------------------------------------------------
// fp32 GEMM: C[M,N] = A[M,K] @ B[K,N] + bias[N]
// 128x128 tile, 256 threads, 8x8 micro-tile, K-chunks of 16.
// ---------------------------------------------------------------------------
__global__ __launch_bounds__(256, 2) void gemm_kernel(
    const float* __restrict__ A, const float* __restrict__ B,
    const float* __restrict__ bias, float* __restrict__ C,
    int M, int N, int K)
{
    __shared__ float As[16][132];
    __shared__ float Bs[16][132];

    const int tid  = threadIdx.x;
    const int m0   = blockIdx.y * 128;
    const int n0   = blockIdx.x * 128;
    const int ty   = tid >> 4, tx = tid & 15;
    const int arow = tid >> 1, aseg = (tid & 1) * 8;
    const int brow = tid >> 4, bcol = (tid & 15) * 4;

    float acc[8][8];
#pragma unroll
    for (int i = 0; i < 8; i++)
#pragma unroll
        for (int j = 0; j < 8; j++) acc[i][j] = 0.f;

    for (int k0 = 0; k0 < K; k0 += 16) {
        float4 av0 = *(const float4*)&A[(size_t)(m0 + arow) * K + k0 + aseg];
        float4 av1 = *(const float4*)&A[(size_t)(m0 + arow) * K + k0 + aseg + 4];
        float4 bv0 = *(const float4*)&B[(size_t)(k0 + brow) * N + n0 + bcol];
        float4 bv1 = *(const float4*)&B[(size_t)(k0 + brow) * N + n0 + bcol + 64];

        As[aseg + 0][arow] = av0.x; As[aseg + 1][arow] = av0.y;
        As[aseg + 2][arow] = av0.z; As[aseg + 3][arow] = av0.w;
        As[aseg + 4][arow] = av1.x; As[aseg + 5][arow] = av1.y;
        As[aseg + 6][arow] = av1.z; As[aseg + 7][arow] = av1.w;
        *(float4*)&Bs[brow][bcol]      = bv0;
        *(float4*)&Bs[brow][bcol + 64] = bv1;
        __syncthreads();

#pragma unroll
        for (int k = 0; k < 16; k++) {
            float a[8], b[8];
            *(float4*)&a[0] = *(const float4*)&As[k][ty * 8];
            *(float4*)&a[4] = *(const float4*)&As[k][ty * 8 + 4];
            *(float4*)&b[0] = *(const float4*)&Bs[k][tx * 8];
            *(float4*)&b[4] = *(const float4*)&Bs[k][tx * 8 + 4];
#pragma unroll
            for (int i = 0; i < 8; i++)
#pragma unroll
                for (int j = 0; j < 8; j++)
                    acc[i][j] = fmaf(a[i], b[j], acc[i][j]);
        }
        __syncthreads();
    }

#pragma unroll
    for (int i = 0; i < 8; i++) {
        size_t row = (size_t)(m0 + ty * 8 + i);
#pragma unroll
        for (int j = 0; j < 8; j += 4) {
            int col = n0 + tx * 8 + j;
            float4 v;
            v.x = acc[i][j + 0] + bias[col + 0];
            v.y = acc[i][j + 1] + bias[col + 1];
            v.z = acc[i][j + 2] + bias[col + 2];
            v.w = acc[i][j + 3] + bias[col + 3];
            *(float4*)&C[row * N + col] = v;
        }
    }
}

// ---------------------------------------------------------------------------
// f32x2 helpers (FFMA2 — SASS packed fp32 FMA, bit-identical per lane)
// ---------------------------------------------------------------------------
__device__ __forceinline__ unsigned long long pack_f2(float lo, float hi) {
    unsigned long long r;
    asm("mov.b64 %0, {%1, %2};" : "=l"(r) : "f"(lo), "f"(hi));
    return r;
}
__device__ __forceinline__ void unpack_f2(unsigned long long v, float& lo, float& hi) {
    asm("mov.b64 {%0, %1}, %2;" : "=f"(lo), "=f"(hi) : "l"(v));
}
__device__ __forceinline__ unsigned long long ffma2(
    unsigned long long a, unsigned long long b, unsigned long long c) {
    unsigned long long d;
    asm("fma.rn.f32x2 %0, %1, %2, %3;" : "=l"(d) : "l"(a), "l"(b), "l"(c));
    return d;
}

__device__ __forceinline__ float sigm(float x) {
    return __fdividef(1.f, 1.f + __expf(-x));
}
__device__ __forceinline__ float tanhe(float x) {
    return 1.f - __fdividef(2.f, __expf(2.f * x) + 1.f);
}

// ---------------------------------------------------------------------------
// Phase 2: persistent LSTM recurrence, 512-thread FFMA2 version.
// Thread (q = tid>>6, c = tid&63): k-slice [q*32, q*32+32) of gate column
//   gcol = gate*256 + r*16 + u  (gate = c>>4, u = c&15).
// h kept PACKED in SMEM: h_s[bp][k] = {h[2bp][k], h[2bp+1][k]} (float2).
// GEMV: 32 FFMA2 per (bp) chain, 4 chains -> 128 FFMA2/thread/step.
// Exchange: pointwise (64 threads, one per (bp,u)) -> packed STG into the
// L2-resident g_Hx ring -> group barrier (fence + atom.release + acquire
// spin by tid0) -> coalesced float4 reload into h_s.
// ---------------------------------------------------------------------------
__global__ __launch_bounds__(NTH, 1)
void lstm_kernel(const float* __restrict__ c0, const float* __restrict__ h0,
                 const float* __restrict__ Whh)
{
    const int g   = blockIdx.x / RC;
    const int r   = blockIdx.x % RC;
    const int tid = threadIdx.x;
    const int q   = tid >> 6;          // k-slice 0..7
    const int c   = tid & 63;          // gate col 0..63
    const int gate = c >> 4, u = c & 15;
    const int gcol = gate * 256 + r * HU + u;

    __shared__ float2 h_s[GBP][HH];        // 8 KB packed h (all 256 k)
    __shared__ float2 red[KQ][GBP][NCC];   // 16 KB per-slice partials

    // One-time: packed Whh slice {w,w} (32 x u64)
    unsigned long long wp[32];
#pragma unroll
    for (int i = 0; i < 32; i++) {
        float w = Whh[(size_t)(q * 32 + i) * FH + gcol];
        wp[i] = pack_f2(w, w);
    }

    // h0 -> packed SMEM
    for (int idx = tid; idx < GBP * HH; idx += NTH) {
        int bp = idx >> 8, k = idx & 255;
        int b0 = g * 8 + 2 * bp;
        h_s[bp][k] = make_float2(h0[(size_t)b0 * HH + k],
                                 h0[(size_t)(b0 + 1) * HH + k]);
    }

    // Pointwise-thread state (tid < 64): (bp, u) pair, c-state packed
    float cx = 0.f, cy = 0.f;
    int pbp = 0, pu = 0;
    size_t gb0 = 0, gb1 = 0, ha0 = 0, ha1 = 0;
    if (tid < 64) {
        pbp = tid >> 4; pu = tid & 15;
        int b0 = g * 8 + 2 * pbp;
        int gu = r * HU + pu;
        cx = c0[(size_t)b0 * HH + gu];
        cy = c0[(size_t)(b0 + 1) * HH + gu];
        gb0 = (size_t)b0 * TT * FH + gu;
        gb1 = (size_t)(b0 + 1) * TT * FH + gu;
        ha0 = (size_t)b0 * TT * HH + gu;
        ha1 = (size_t)(b0 + 1) * TT * HH + gu;
    }
    __syncthreads();

    unsigned target = 0;

    for (int t = 0; t < TT; t++) {
        // Prefetch this step's x@Wih+bh gate contributions (DRAM, used late)
        float pi0 = 0.f, pf0 = 0.f, pg0 = 0.f, po0 = 0.f;
        float pi1 = 0.f, pf1 = 0.f, pg1 = 0.f, po1 = 0.f;
        if (tid < 64) {
            const float* ga = &g_G[gb0 + (size_t)t * FH];
            const float* gb = &g_G[gb1 + (size_t)t * FH];
            pi0 = ga[0]; pf0 = ga[256]; pg0 = ga[512]; po0 = ga[768];
            pi1 = gb[0]; pf1 = gb[256]; pg1 = gb[512]; po1 = gb[768];
        }

        // ---- GEMV: 4 packed batch-pair chains, 32 k each (FFMA2) ----
        {
            const float4* h0p = (const float4*)&h_s[0][q * 32];
            const float4* h1p = (const float4*)&h_s[1][q * 32];
            const float4* h2p = (const float4*)&h_s[2][q * 32];
            const float4* h3p = (const float4*)&h_s[3][q * 32];
            unsigned long long a0 = 0ull, a1 = 0ull, a2 = 0ull, a3 = 0ull;
#pragma unroll
            for (int i = 0; i < 16; i++) {
                float4 v0 = h0p[i], v1 = h1p[i], v2 = h2p[i], v3 = h3p[i];
                a0 = ffma2(pack_f2(v0.x, v0.y), wp[2 * i],     a0);
                a1 = ffma2(pack_f2(v1.x, v1.y), wp[2 * i],     a1);
                a2 = ffma2(pack_f2(v2.x, v2.y), wp[2 * i],     a2);
                a3 = ffma2(pack_f2(v3.x, v3.y), wp[2 * i],     a3);
                a0 = ffma2(pack_f2(v0.z, v0.w), wp[2 * i + 1], a0);
                a1 = ffma2(pack_f2(v1.z, v1.w), wp[2 * i + 1], a1);
                a2 = ffma2(pack_f2(v2.z, v2.w), wp[2 * i + 1], a2);
                a3 = ffma2(pack_f2(v3.z, v3.w), wp[2 * i + 1], a3);
            }
            float lo, hi;
            unpack_f2(a0, lo, hi); red[q][0][c] = make_float2(lo, hi);
            unpack_f2(a1, lo, hi); red[q][1][c] = make_float2(lo, hi);
            unpack_f2(a2, lo, hi); red[q][2][c] = make_float2(lo, hi);
            unpack_f2(a3, lo, hi); red[q][3][c] = make_float2(lo, hi);
        }
        __syncthreads();

        // ---- Reduce 8 k-slices + LSTM cell (64 threads, 2 batches each) ----
        if (tid < 64) {
            float vi0 = pi0, vi1 = pi1, vf0 = pf0, vf1 = pf1;
            float vg0 = pg0, vg1 = pg1, vo0 = po0, vo1 = po1;
#pragma unroll
            for (int qq = 0; qq < KQ; qq++) {
                float2 xi = red[qq][pbp][pu];
                float2 xf = red[qq][pbp][16 + pu];
                float2 xg = red[qq][pbp][32 + pu];
                float2 xo = red[qq][pbp][48 + pu];
                vi0 += xi.x; vi1 += xi.y;
                vf0 += xf.x; vf1 += xf.y;
                vg0 += xg.x; vg1 += xg.y;
                vo0 += xo.x; vo1 += xo.y;
            }
            cx = sigm(vf0) * cx + sigm(vi0) * tanhe(vg0);
            cy = sigm(vf1) * cy + sigm(vi1) * tanhe(vg1);
            float hx = sigm(vo0) * tanhe(cx);
            float hy = sigm(vo1) * tanhe(cy);

            // phase-3 stream (fire and forget)
            g_Hall[ha0 + (size_t)t * HH] = hx;
            g_Hall[ha1 + (size_t)t * HH] = hy;
            // packed exchange ring (L2-resident)
            *(float2*)&g_Hx[t & 1][g][pbp][2 * (r * HU + pu)] =
                make_float2(hx, hy);
        }
        __syncthreads();

        // ---- Group barrier: publish + arrive + wait (tid 0 only) ----
        target += RC;
        if (tid == 0) {
            asm volatile("fence.acq_rel.gpu;" ::: "memory");
            unsigned old;
            asm volatile("atom.add.release.gpu.u32 %0, [%1], %2;"
                         : "=r"(old) : "l"(&g_ctr[g]), "r"(1u) : "memory");
            unsigned v;
            do {
                asm volatile("ld.acquire.gpu.u32 %0, [%1];"
                             : "=r"(v) : "l"(&g_ctr[g]) : "memory");
            } while (v < target);
        }
        __syncthreads();

        // ---- Coalesced reload of the full packed h_t ----
        {
            int bp  = tid >> 7;
            int off = (tid & 127) * 4;
            float4 v = *(const float4*)&g_Hx[t & 1][g][bp][off];
            *(float4*)((float*)&h_s[bp][0] + off) = v;
        }
        __syncthreads();
    }
}

// ---------------------------------------------------------------------------
// Launch: init -> G = x@Wih + bh -> LSTM recurrence -> Y = Hall@Wout + bout
// Inputs (metadata order): x, c0, h0, Wih, Whh, bh, Wout, bout
// ---------------------------------------------------------------------------
extern "C" void kernel_launch(void* const* d_in, const int* in_sizes, int n_in,
                              void* d_out, int out_size)
{
    const float* x    = (const float*)d_in[0];
    const float* c0   = (const float*)d_in[1];
    const float* h0   = (const float*)d_in[2];
    const float* Wih  = (const float*)d_in[3];
    const float* Whh  = (const float*)d_in[4];
    const float* bh   = (const float*)d_in[5];
    const float* Wout = (const float*)d_in[6];
    const float* bout = (const float*)d_in[7];
    float* Y = (float*)d_out;

    float* Gp = nullptr;
    float* Hp = nullptr;
    cudaGetSymbolAddress((void**)&Gp, g_G);
    cudaGetSymbolAddress((void**)&Hp, g_Hall);

    init_kernel<<<1, 32>>>();

    // Phase 1: G[B*T, 4H] = x[B*T, D] @ Wih[D, 4H] + bh
    {
        dim3 grid(FH / 128, (BB * TT) / 128);
        gemm_kernel<<<grid, 256>>>(x, Wih, bh, Gp, BB * TT, FH, DD);
    }

    // Phase 2: sequential LSTM over T steps (8 groups x 16 CTAs, 512 thr)
    lstm_kernel<<<NGRP * RC, NTH>>>(c0, h0, Whh);

    // Phase 3: Y[B*T, O] = Hall[B*T, H] @ Wout[H, O] + bout
    {
        dim3 grid(OO / 128, (BB * TT) / 128);
        gemm_kernel<<<grid, 256>>>(Hp, Wout, bout, Y, BB * TT, OO, HH);
    }
}